// round 2
// baseline (speedup 1.0000x reference)
#include <cuda_runtime.h>

#define MAX_N 65536

__device__ float g_p[MAX_N];    // x . w_rel  per node
__device__ float g_r[MAX_N];    // x . w_root per node
__device__ float g_agg[MAX_N];  // scatter-add of p over edges

// ---------------------------------------------------------------------------
// Kernel 1: per-node dual dot products (warp per node), also zeroes g_agg.
// ---------------------------------------------------------------------------
__global__ void k_scores(const float* __restrict__ x,
                         const float* __restrict__ wrel,
                         const float* __restrict__ wroot,
                         int N, int d) {
    int warp = (blockIdx.x * blockDim.x + threadIdx.x) >> 5;
    int lane = threadIdx.x & 31;
    if (warp >= N) return;
    const float* xr = x + (size_t)warp * d;
    float sp = 0.f, sr = 0.f;
    // d is a multiple of 128 here (d=256): 2 float4 per lane
    for (int c = lane * 4; c < d; c += 128) {
        float4 xv = *reinterpret_cast<const float4*>(xr + c);
        float4 wa = *reinterpret_cast<const float4*>(wrel + c);
        float4 wb = *reinterpret_cast<const float4*>(wroot + c);
        sp += xv.x * wa.x + xv.y * wa.y + xv.z * wa.z + xv.w * wa.w;
        sr += xv.x * wb.x + xv.y * wb.y + xv.z * wb.z + xv.w * wb.w;
    }
#pragma unroll
    for (int o = 16; o; o >>= 1) {
        sp += __shfl_xor_sync(0xffffffffu, sp, o);
        sr += __shfl_xor_sync(0xffffffffu, sr, o);
    }
    if (lane == 0) {
        g_p[warp] = sp;
        g_r[warp] = sr;
        g_agg[warp] = 0.f;
    }
}

// ---------------------------------------------------------------------------
// Kernel 2: scalar edge scatter-add (the algebraic collapse of segment_sum@w_rel)
// ---------------------------------------------------------------------------
__global__ void k_edges(const int* __restrict__ src, const int* __restrict__ dst, int E) {
    int e = blockIdx.x * blockDim.x + threadIdx.x;
    if (e < E) atomicAdd(&g_agg[dst[e]], g_p[src[e]]);
}

// ---------------------------------------------------------------------------
// Kernel 3 (fused): per-graph tanh scores -> exact top-k (bitonic sort of
// packed keys) -> weighted mean of selected rows -> output projection.
// One block per graph.
// Dynamic smem layout: [ keys: NP2 * u64 | vals: k f32 | idxs: k i32 | pooled: d f32 ]
// ---------------------------------------------------------------------------
__global__ void k_pool(const float* __restrict__ x,
                       const float* __restrict__ brel,
                       const float* __restrict__ wproj,
                       const float* __restrict__ bproj,
                       float* __restrict__ out,
                       int n, int k, int NP2, int d, int odim) {
    extern __shared__ unsigned char sm[];
    unsigned long long* keys = (unsigned long long*)sm;
    float* vals = (float*)(sm + (size_t)NP2 * 8);
    int* idxs = (int*)(vals + k);
    float* pooled = (float*)(idxs + k);

    const int g = blockIdx.x;
    const int tid = threadIdx.x;
    const int base = g * n;
    const float br = brel[0];

    // --- build sortable keys: high 32 = order-preserving float bits,
    //     low 32 = (n-1-idx) so that on ties the SMALLER index sorts HIGHER
    //     (matches jax.lax.top_k tie-breaking). Padding = 0 (below any real key).
    for (int i = tid; i < NP2; i += blockDim.x) {
        unsigned long long key = 0ull;
        if (i < n) {
            float s = tanhf(g_agg[base + i] + br + g_r[base + i]);
            unsigned u = __float_as_uint(s);
            u = (u & 0x80000000u) ? ~u : (u | 0x80000000u);
            key = ((unsigned long long)u << 32) | (unsigned)(n - 1 - i);
        }
        keys[i] = key;
    }
    __syncthreads();

    // --- bitonic sort ascending (top-k ends up in keys[NP2-k .. NP2))
    for (int kk = 2; kk <= NP2; kk <<= 1) {
        for (int j = kk >> 1; j > 0; j >>= 1) {
            for (int e = tid; e < NP2; e += blockDim.x) {
                int pa = e ^ j;
                if (pa > e) {
                    bool up = ((e & kk) == 0);
                    unsigned long long a = keys[e], b = keys[pa];
                    if ((a > b) == up) { keys[e] = b; keys[pa] = a; }
                }
            }
            __syncthreads();
        }
    }

    // --- decode selected (value, node index) pairs
    for (int j = tid; j < k; j += blockDim.x) {
        unsigned long long key = keys[NP2 - k + j];
        unsigned hu = (unsigned)(key >> 32);
        unsigned fu = (hu & 0x80000000u) ? (hu & 0x7fffffffu) : ~hu;
        vals[j] = __uint_as_float(fu);
        idxs[j] = n - 1 - (int)(key & 0xffffffffu);
    }
    __syncthreads();

    // --- weighted mean over the k kept nodes: pooled[col] = (1/k) sum_j val_j * x[sel_j][col]
    // 4 independent accumulators for memory-level parallelism.
    const float inv_k = 1.0f / (float)k;
    for (int col = tid; col < d; col += blockDim.x) {
        float a0 = 0.f, a1 = 0.f, a2 = 0.f, a3 = 0.f;
        int j = 0;
        for (; j + 4 <= k; j += 4) {
            a0 += vals[j + 0] * x[(size_t)(base + idxs[j + 0]) * d + col];
            a1 += vals[j + 1] * x[(size_t)(base + idxs[j + 1]) * d + col];
            a2 += vals[j + 2] * x[(size_t)(base + idxs[j + 2]) * d + col];
            a3 += vals[j + 3] * x[(size_t)(base + idxs[j + 3]) * d + col];
        }
        for (; j < k; j++)
            a0 += vals[j] * x[(size_t)(base + idxs[j]) * d + col];
        pooled[col] = (a0 + a1 + a2 + a3) * inv_k;
    }
    __syncthreads();

    // --- output projection: out[g, o] = b_proj[o] + sum_d pooled[d] * w_proj[d, o]
    for (int o = tid; o < odim; o += blockDim.x) {
        float acc = bproj[o];
#pragma unroll 4
        for (int dd = 0; dd < d; dd++)
            acc += pooled[dd] * wproj[(size_t)dd * odim + o];
        out[(size_t)g * odim + o] = acc;
    }
}

// ---------------------------------------------------------------------------
// Launch. Input order (metadata): x, edge_index, batch, num_graphs,
// w_rel, b_rel, w_root, w_proj, b_proj. Output: [B, out_dim] float32.
// ---------------------------------------------------------------------------
extern "C" void kernel_launch(void* const* d_in, const int* in_sizes, int n_in,
                              void* d_out, int out_size) {
    const float* x     = (const float*)d_in[0];
    const int*   ei    = (const int*)d_in[1];
    const float* wrel  = (const float*)d_in[4];
    const float* brel  = (const float*)d_in[5];
    const float* wroot = (const float*)d_in[6];
    const float* wproj = (const float*)d_in[7];
    const float* bproj = (const float*)d_in[8];
    float* out = (float*)d_out;

    const int odim = in_sizes[8];               // out_dim from b_proj
    const int d    = in_sizes[7] / odim;        // feat dim from w_proj
    const int N    = in_sizes[0] / d;           // total nodes
    const int E    = in_sizes[1] / 2;           // total edges
    const int B    = out_size / odim;           // graphs
    const int n    = N / B;                     // nodes per graph (equal-size)
    const int k    = (n + 1) / 2;               // ceil(0.5 * n)  (RATIO = 0.5)
    int NP2 = 1;
    while (NP2 < n) NP2 <<= 1;

    // K1: warp per node
    k_scores<<<(N + 7) / 8, 256>>>(x, wrel, wroot, N, d);
    // K2: scalar edge scatter
    k_edges<<<(E + 255) / 256, 256>>>(ei, ei + E, E);
    // K3: fused tanh + topk + weighted mean + projection, one block per graph
    size_t smem = (size_t)NP2 * 8 + (size_t)k * 8 + (size_t)d * 4;
    k_pool<<<B, 256, smem>>>(x, brel, wproj, bproj, out, n, k, NP2, d, odim);
}

// round 3
// speedup vs baseline: 2.1841x; 2.1841x over previous
#include <cuda_runtime.h>

#define MAX_N 65536

__device__ float g_p[MAX_N];    // x . w_rel  per node
__device__ float g_r[MAX_N];    // x . w_root per node
__device__ float g_agg[MAX_N];  // scatter-add of p over edges

// ---------------------------------------------------------------------------
// Kernel 1: per-node dual dot products. 8 lanes per node (4 nodes per warp),
// fully unrolled -> ~24 LDG.128 in flight per thread. Also zeroes g_agg.
// ---------------------------------------------------------------------------
__global__ void k_scores(const float4* __restrict__ x4,
                         const float4* __restrict__ wrel4,
                         const float4* __restrict__ wroot4,
                         int N, int d4) {
    int warp = (blockIdx.x * blockDim.x + threadIdx.x) >> 5;
    int lane = threadIdx.x & 31;
    int sub  = lane >> 3;          // node within warp (0..3)
    int l8   = lane & 7;           // lane within node-segment
    int node = warp * 4 + sub;
    if (node >= N) return;

    const float4* xr = x4 + (size_t)node * d4;
    float sp = 0.f, sr = 0.f;
#pragma unroll 8
    for (int c = l8; c < d4; c += 8) {
        float4 xv = xr[c];
        float4 wa = wrel4[c];
        float4 wb = wroot4[c];
        sp += xv.x * wa.x + xv.y * wa.y + xv.z * wa.z + xv.w * wa.w;
        sr += xv.x * wb.x + xv.y * wb.y + xv.z * wb.z + xv.w * wb.w;
    }
#pragma unroll
    for (int o = 4; o; o >>= 1) {
        sp += __shfl_xor_sync(0xffffffffu, sp, o);
        sr += __shfl_xor_sync(0xffffffffu, sr, o);
    }
    if (l8 == 0) {
        g_p[node]   = sp;
        g_r[node]   = sr;
        g_agg[node] = 0.f;
    }
}

// ---------------------------------------------------------------------------
// Kernel 2: scalar edge scatter-add (algebraic collapse of segment_sum @ w_rel)
// ---------------------------------------------------------------------------
__global__ void k_edges(const int* __restrict__ src, const int* __restrict__ dst, int E) {
    int e = blockIdx.x * blockDim.x + threadIdx.x;
    if (e < E) atomicAdd(&g_agg[dst[e]], g_p[src[e]]);
}

// ---------------------------------------------------------------------------
// Kernel 3 (fused, 1024 threads / graph):
//   tanh scores -> rank-based exact top-k SET selection (O(n^2) count, no sort)
//   -> weighted mean over 4 node-replicas (8 accumulators each)
//   -> output projection split 4-ways over d.
// Ties follow jax.lax.top_k (smaller index wins) via packed (score|inv-idx) keys.
// Dynamic smem: [keys: n u64 | svals: k f32 | sidx: k i32 | part: 4*d f32 | pooled: d f32 | cnt: 1 i32]
// ---------------------------------------------------------------------------
__global__ void k_pool(const float* __restrict__ x,
                       const float* __restrict__ brel,
                       const float* __restrict__ wproj,
                       const float* __restrict__ bproj,
                       float* __restrict__ out,
                       int n, int k, int d, int odim) {
    extern __shared__ unsigned char sm[];
    unsigned long long* keys = (unsigned long long*)sm;
    float* svals  = (float*)(keys + n);
    int*   sidx   = (int*)(svals + k);
    float* part   = (float*)(sidx + k);        // 4 * d
    float* pooled = part + 4 * d;              // d
    int*   cnt    = (int*)(pooled + d);

    const int g    = blockIdx.x;
    const int tid  = threadIdx.x;
    const int base = g * n;
    const float br = brel[0];

    if (tid == 0) *cnt = 0;

    // --- scores + sortable keys (high: order-preserving float bits, low: n-1-i)
    float myscore = 0.f;
    if (tid < n) {
        myscore = tanhf(g_agg[base + tid] + br + g_r[base + tid]);
        unsigned u = __float_as_uint(myscore);
        u = (u & 0x80000000u) ? ~u : (u | 0x80000000u);
        keys[tid] = ((unsigned long long)u << 32) | (unsigned)(n - 1 - tid);
    }
    __syncthreads();

    // --- rank = #keys strictly greater; unique keys => rank<k iff in top-k set
    if (tid < n) {
        unsigned long long my = keys[tid];
        int rank = 0;
#pragma unroll 8
        for (int j = 0; j < n; j++)
            rank += (keys[j] > my);
        if (rank < k) {
            int pos = atomicAdd(cnt, 1);
            svals[pos] = myscore;
            sidx[pos]  = tid;
        }
    }
    __syncthreads();

    // --- weighted mean: 4 replicas over nodes x d columns, 8 accumulators
    {
        const int col = tid & (d - 1);         // d is power of two (256)
        const int rep = tid >> 8;              // 0..3 (blockDim = 1024, d = 256)
        const int per = (k + 3) >> 2;
        const int j0  = rep * per;
        const int j1  = min(j0 + per, k);
        float a[8];
#pragma unroll
        for (int u = 0; u < 8; u++) a[u] = 0.f;
        int j = j0;
        for (; j + 8 <= j1; j += 8) {
#pragma unroll
            for (int u = 0; u < 8; u++)
                a[u] += svals[j + u] * x[(size_t)(base + sidx[j + u]) * d + col];
        }
        for (; j < j1; j++)
            a[0] += svals[j] * x[(size_t)(base + sidx[j]) * d + col];
        float s = 0.f;
#pragma unroll
        for (int u = 0; u < 8; u++) s += a[u];
        part[rep * d + col] = s;
    }
    __syncthreads();

    if (tid < d) {
        float inv_k = 1.0f / (float)k;
        pooled[tid] = (part[tid] + part[d + tid] + part[2 * d + tid] + part[3 * d + tid]) * inv_k;
    }
    __syncthreads();

    // --- projection: out[g,o] = b[o] + sum_dd pooled[dd]*wproj[dd,o], split 4-ways
    {
        const int o   = tid & (odim - 1);
        const int p   = tid >> 8;
        const int per = (d + 3) >> 2;
        const int d0  = p * per;
        const int d1  = min(d0 + per, d);
        float acc = 0.f;
        int dd = d0;
        for (; dd + 8 <= d1; dd += 8) {
#pragma unroll
            for (int u = 0; u < 8; u++)
                acc += pooled[dd + u] * wproj[(size_t)(dd + u) * odim + o];
        }
        for (; dd < d1; dd++)
            acc += pooled[dd] * wproj[(size_t)dd * odim + o];
        part[p * odim + o] = acc;   // reuse part[] as projection partials
    }
    __syncthreads();

    if (tid < odim)
        out[(size_t)g * odim + tid] =
            bproj[tid] + part[tid] + part[odim + tid] + part[2 * odim + tid] + part[3 * odim + tid];
}

// ---------------------------------------------------------------------------
// Launch. Inputs: x, edge_index, batch, num_graphs, w_rel, b_rel, w_root,
// w_proj, b_proj. Output: [B, out_dim] float32.
// ---------------------------------------------------------------------------
extern "C" void kernel_launch(void* const* d_in, const int* in_sizes, int n_in,
                              void* d_out, int out_size) {
    const float* x     = (const float*)d_in[0];
    const int*   ei    = (const int*)d_in[1];
    const float* wrel  = (const float*)d_in[4];
    const float* brel  = (const float*)d_in[5];
    const float* wroot = (const float*)d_in[6];
    const float* wproj = (const float*)d_in[7];
    const float* bproj = (const float*)d_in[8];
    float* out = (float*)d_out;

    const int odim = in_sizes[8];
    const int d    = in_sizes[7] / odim;
    const int N    = in_sizes[0] / d;
    const int E    = in_sizes[1] / 2;
    const int B    = out_size / odim;
    const int n    = N / B;
    const int k    = (n + 1) / 2;   // ceil(0.5 * n), RATIO = 0.5

    // K1: 8 lanes per node (4 nodes/warp)
    int warps = (N + 3) / 4;
    k_scores<<<(warps * 32 + 255) / 256, 256>>>(
        (const float4*)x, (const float4*)wrel, (const float4*)wroot, N, d / 4);
    // K2: scalar edge scatter
    k_edges<<<(E + 255) / 256, 256>>>(ei, ei + E, E);
    // K3: fused select + pool + project, 1024 threads per graph
    size_t smem = (size_t)n * 8 + (size_t)k * 8 + (size_t)(5 * d) * 4 + 16;
    k_pool<<<B, 1024, smem>>>(x, brel, wproj, bproj, out, n, k, d, odim);
}